// round 15
// baseline (speedup 1.0000x reference)
#include <cuda_runtime.h>
#include <cuda_bf16.h>
#include <math.h>
#include <cstdint>

// NT-Xent loss, symmetry-packed HMMA with PERSISTENT WORK QUEUE:
// 148 CTAs pull single 128x128 upper-triangle tiles (2080 items) from a global
// atomic counter -> near-ideal SM load balance. A operand pre-scaled by
// 2*log2(e) so the epilogue is a bare ex2.
//   K1: normalize -> g_znh (bf16) and g_znA (bf16, x 2log2e); zero accums+ctr
//   K2: per tile: bf16 MMA, exp, row sums (block I) + col sums (block J) via
//       shfl + atomicAdd; pos extracted on tiles J==I+32
//   K3: mean(log(sumexp) - pos)

#define D_DIM     128
#define N_MAX     8192
#define NT_TILES  2080          // 64*65/2
#define GRID2     148
#define LOG2E_X2  2.885390081777927f
#define LN2F      0.6931471805599453f

__device__ __nv_bfloat16 g_znh[N_MAX * D_DIM];   // normalized (B operand)
__device__ __nv_bfloat16 g_znA[N_MAX * D_DIM];   // normalized * 2log2e (A operand)
__device__ float g_sumexp[N_MAX];
__device__ float g_pos[N_MAX];
__device__ int   g_workctr;

// ------------------------------------------------------------- helpers
__device__ __forceinline__ uint32_t smem_u32(const void* p) {
    uint32_t a;
    asm("{ .reg .u64 t; cvta.to.shared.u64 t, %1; cvt.u32.u64 %0, t; }" : "=r"(a) : "l"(p));
    return a;
}
__device__ __forceinline__ void cp_async16(uint32_t saddr, const void* gaddr) {
    asm volatile("cp.async.cg.shared.global [%0], [%1], 16;" :: "r"(saddr), "l"(gaddr));
}
#define CP_COMMIT() asm volatile("cp.async.commit_group;" ::: "memory")
#define CP_WAIT(n)  asm volatile("cp.async.wait_group %0;" :: "n"(n) : "memory")

__device__ __forceinline__ void ldsm_x4(uint32_t* r, uint32_t addr) {
    asm volatile("ldmatrix.sync.aligned.m8n8.x4.shared.b16 {%0,%1,%2,%3}, [%4];"
                 : "=r"(r[0]), "=r"(r[1]), "=r"(r[2]), "=r"(r[3]) : "r"(addr));
}
__device__ __forceinline__ void mma16816(float* d, const uint32_t* a, const uint32_t* b) {
    asm volatile(
        "mma.sync.aligned.m16n8k16.row.col.f32.bf16.bf16.f32 "
        "{%0,%1,%2,%3}, {%4,%5,%6,%7}, {%8,%9}, {%0,%1,%2,%3};"
        : "+f"(d[0]), "+f"(d[1]), "+f"(d[2]), "+f"(d[3])
        : "r"(a[0]), "r"(a[1]), "r"(a[2]), "r"(a[3]), "r"(b[0]), "r"(b[1]));
}
__device__ __forceinline__ float ex2(float x) {
    float e;
    asm("ex2.approx.ftz.f32 %0, %1;" : "=f"(e) : "f"(x));
    return e;
}
__device__ __forceinline__ uint32_t tile_addr(uint32_t base, int row, int chunk) {
    return base + row * 256 + (((uint32_t)(chunk ^ (row & 7))) << 4);
}
// triangular row offset: tiles before row i
__device__ __forceinline__ int tri_off(int i) { return 64 * i - (i * (i - 1)) / 2; }
__device__ __forceinline__ void decode_tile(int idx, int& I, int& J) {
    int i = (int)(64.5f - sqrtf(4160.25f - 2.0f * (float)idx));
    if (i < 0) i = 0;
    while (i > 0 && tri_off(i) > idx) i--;
    while (tri_off(i + 1) <= idx) i++;
    I = i;
    J = i + (idx - tri_off(i));
}

// ------------------------------------------------------------- K1
__global__ void ntx_normalize(const float* __restrict__ zi,
                              const float* __restrict__ zj, int Bv) {
    int gt = blockIdx.x * blockDim.x + threadIdx.x;
    int Nv = 2 * Bv;
    if (gt < Nv) { g_sumexp[gt] = 0.f; g_pos[gt] = 0.f; }
    if (gt == 0) g_workctr = GRID2;
    int warp = gt >> 5;
    int lane = threadIdx.x & 31;
    if (warp >= Nv) return;
    const float* src = (warp < Bv) ? (zi + (size_t)warp * D_DIM)
                                   : (zj + (size_t)(warp - Bv) * D_DIM);
    float4 v = ((const float4*)src)[lane];
    float ss = v.x * v.x + v.y * v.y + v.z * v.z + v.w * v.w;
#pragma unroll
    for (int o = 16; o; o >>= 1) ss += __shfl_xor_sync(0xFFFFFFFFu, ss, o);
    float rn = 1.0f / fmaxf(sqrtf(ss), 1e-12f);
    // B operand: normalized
    {
        __nv_bfloat162 p0 = __float22bfloat162_rn(make_float2(v.x * rn, v.y * rn));
        __nv_bfloat162 p1 = __float22bfloat162_rn(make_float2(v.z * rn, v.w * rn));
        uint2 out; out.x = *(uint32_t*)&p0; out.y = *(uint32_t*)&p1;
        ((uint2*)(g_znh + (size_t)warp * D_DIM))[lane] = out;
    }
    // A operand: normalized * 2log2e
    {
        float rs = rn * LOG2E_X2;
        __nv_bfloat162 p0 = __float22bfloat162_rn(make_float2(v.x * rs, v.y * rs));
        __nv_bfloat162 p1 = __float22bfloat162_rn(make_float2(v.z * rs, v.w * rs));
        uint2 out; out.x = *(uint32_t*)&p0; out.y = *(uint32_t*)&p1;
        ((uint2*)(g_znA + (size_t)warp * D_DIM))[lane] = out;
    }
}

// ------------------------------------------------------------- K2
// smem: 2 slots x (A 32KB + B 32KB)
#define SLOT_SZ  65536
#define SMEM_REQ 132096

__device__ __forceinline__ void issue_tile(uint32_t sdst, const __nv_bfloat16* gsrc,
                                           int srcRow, int tid) {
    int r = tid >> 1, h = tid & 1;
    const char* g = (const char*)(gsrc + (size_t)(srcRow + r) * D_DIM + h * 64);
    uint32_t srow = sdst + r * 256;
#pragma unroll
    for (int i = 0; i < 8; i++) {
        int c = h * 8 + i;
        cp_async16(srow + (((uint32_t)(c ^ (r & 7))) << 4), g + i * 16);
    }
}
__device__ __forceinline__ void issue_item(uint32_t slot, int I, int J, int tid) {
    issue_tile(slot, g_znA, I * 128, tid);
    if (J != I) issue_tile(slot + 32768, g_znh, J * 128, tid);
}

__global__ __launch_bounds__(256, 1) void ntx_simloss(int Bv) {
    extern __shared__ char smraw[];
    __shared__ int s_idx;
    uint32_t raw = smem_u32(smraw);
    uint32_t base = (raw + 1023u) & ~1023u;

    const int tid = threadIdx.x, lane = tid & 31, wid = tid >> 5;
    const int wm = (wid & 3) * 32;
    const int wn = (wid >> 2) * 64;

    int cur = blockIdx.x;                 // first item (GRID2 <= NT_TILES)
    int Ic, Jc; decode_tile(cur, Ic, Jc);
    issue_item(base, Ic, Jc, tid);
    CP_COMMIT();
    if (tid == 0) s_idx = atomicAdd(&g_workctr, 1);
    __syncthreads();
    int nxt = s_idx;
    bool vn = (nxt < NT_TILES);
    int In = 0, Jn = 0;
    if (vn) { decode_tile(nxt, In, Jn); issue_item(base + SLOT_SZ, In, Jn, tid); }
    CP_COMMIT();

    int p = 0;
    while (true) {
        CP_WAIT(1);
        __syncthreads();

        if (tid == 0) s_idx = atomicAdd(&g_workctr, 1);   // hidden under compute

        const uint32_t slot = base + (uint32_t)p * SLOT_SZ;
        const uint32_t Ab = slot;
        const uint32_t Bb = (Jc == Ic) ? slot : slot + 32768;
        const bool isDiag = (Jc == Ic), isPos = (Jc == Ic + 32);

        // ---- MMA
        float acc[2][8][4];
#pragma unroll
        for (int mt = 0; mt < 2; mt++)
#pragma unroll
            for (int nt = 0; nt < 8; nt++)
#pragma unroll
                for (int e = 0; e < 4; e++) acc[mt][nt][e] = 0.f;
#pragma unroll
        for (int ks = 0; ks < 8; ks++) {
            uint32_t a[2][4];
#pragma unroll
            for (int mt = 0; mt < 2; mt++)
                ldsm_x4(a[mt], tile_addr(Ab, wm + mt * 16 + (lane & 15),
                                         ks * 2 + (lane >> 4)));
            uint32_t b[4][4];
#pragma unroll
            for (int np = 0; np < 4; np++)
                ldsm_x4(b[np], tile_addr(Bb,
                                         wn + (np * 2 + (lane >> 4)) * 8 + (lane & 7),
                                         ks * 2 + ((lane >> 3) & 1)));
#pragma unroll
            for (int mt = 0; mt < 2; mt++)
#pragma unroll
                for (int np = 0; np < 4; np++) {
                    mma16816(acc[mt][np * 2],     a[mt], &b[np][0]);
                    mma16816(acc[mt][np * 2 + 1], a[mt], &b[np][2]);
                }
        }

        // ---- epilogue (acc is already 2log2e * dot; ev = exp(sim/T))
        float rAcc[2][2] = {{0.f, 0.f}, {0.f, 0.f}};
        float cAcc[8][2];
#pragma unroll
        for (int nt = 0; nt < 8; nt++) { cAcc[nt][0] = 0.f; cAcc[nt][1] = 0.f; }

        if (!isDiag && !isPos) {
#pragma unroll
            for (int mt = 0; mt < 2; mt++)
#pragma unroll
                for (int nt = 0; nt < 8; nt++)
#pragma unroll
                    for (int e = 0; e < 4; e++) {
                        float ev = ex2(acc[mt][nt][e]);
                        rAcc[mt][e >> 1] += ev;
                        cAcc[nt][e & 1] += ev;
                    }
        } else if (isDiag) {
#pragma unroll
            for (int mt = 0; mt < 2; mt++) {
                int r0 = wm + mt * 16 + (lane >> 2);
#pragma unroll
                for (int nt = 0; nt < 8; nt++) {
                    int c0 = wn + nt * 8 + 2 * (lane & 3);
#pragma unroll
                    for (int e = 0; e < 4; e++) {
                        int r = r0 + ((e >> 1) << 3);
                        int c = c0 + (e & 1);
                        float ev = ex2(acc[mt][nt][e]);
                        if (r != c) rAcc[mt][e >> 1] += ev;
                    }
                }
            }
        } else {  // pos tile
#pragma unroll
            for (int mt = 0; mt < 2; mt++) {
                int r0 = wm + mt * 16 + (lane >> 2);
#pragma unroll
                for (int nt = 0; nt < 8; nt++) {
                    int c0 = wn + nt * 8 + 2 * (lane & 3);
#pragma unroll
                    for (int e = 0; e < 4; e++) {
                        int r = r0 + ((e >> 1) << 3);
                        int c = c0 + (e & 1);
                        float v = acc[mt][nt][e];
                        float ev = ex2(v);
                        rAcc[mt][e >> 1] += ev;
                        cAcc[nt][e & 1] += ev;
                        if (r == c) {
                            float vp = v * LN2F;          // = sim/T
                            atomicAdd(&g_pos[Ic * 128 + r], vp);
                            atomicAdd(&g_pos[Jc * 128 + r], vp);
                        }
                    }
                }
            }
        }

        // ---- row flush (block I)
#pragma unroll
        for (int mt = 0; mt < 2; mt++)
#pragma unroll
            for (int h = 0; h < 2; h++) {
                float v = rAcc[mt][h];
                v += __shfl_xor_sync(0xFFFFFFFFu, v, 1);
                v += __shfl_xor_sync(0xFFFFFFFFu, v, 2);
                if ((lane & 3) == 0)
                    atomicAdd(&g_sumexp[Ic * 128 + wm + mt * 16 + h * 8 + (lane >> 2)], v);
            }
        // ---- col flush (block J); skip on diagonal
        if (!isDiag) {
#pragma unroll
            for (int nt = 0; nt < 8; nt++)
#pragma unroll
                for (int e1 = 0; e1 < 2; e1++) {
                    float s = cAcc[nt][e1];
                    s += __shfl_xor_sync(0xFFFFFFFFu, s, 4);
                    s += __shfl_xor_sync(0xFFFFFFFFu, s, 8);
                    s += __shfl_xor_sync(0xFFFFFFFFu, s, 16);
                    if ((lane >> 2) == 0)
                        atomicAdd(&g_sumexp[Jc * 128 + wn + nt * 8 + 2 * (lane & 3) + e1], s);
                }
        }

        __syncthreads();   // compute done: buffer p reusable, s_idx visible
        if (!vn) break;
        int fol = s_idx;
        cur = nxt; Ic = In; Jc = Jn;
        bool vf = (fol < NT_TILES);
        if (vf) { decode_tile(fol, In, Jn); issue_item(base + (uint32_t)p * SLOT_SZ, In, Jn, tid); }
        CP_COMMIT();
        vn = vf; nxt = fol;
        p ^= 1;
    }
}

// ------------------------------------------------------------- K3
__global__ void ntx_finalize(float* __restrict__ out, int Bv) {
    const int Nv = 2 * Bv;
    __shared__ float red[256];
    float acc = 0.f;
    for (int r = threadIdx.x; r < Nv; r += blockDim.x)
        acc += (logf(g_sumexp[r]) - g_pos[r]);
    red[threadIdx.x] = acc;
    __syncthreads();
    for (int s = 128; s > 0; s >>= 1) {
        if (threadIdx.x < s) red[threadIdx.x] += red[threadIdx.x + s];
        __syncthreads();
    }
    if (threadIdx.x == 0) out[0] = red[0] / (float)Nv;
}

// ------------------------------------------------------------- launch
extern "C" void kernel_launch(void* const* d_in, const int* in_sizes, int n_in,
                              void* d_out, int out_size) {
    const float* zi = (const float*)d_in[0];
    const float* zj = (const float*)d_in[1];
    const int Bv = in_sizes[0] / D_DIM;   // 4096
    const int Nv = 2 * Bv;                // 8192

    cudaFuncSetAttribute(ntx_simloss, cudaFuncAttributeMaxDynamicSharedMemorySize, SMEM_REQ);

    ntx_normalize<<<Nv / 8, 256>>>(zi, zj, Bv);
    ntx_simloss<<<GRID2, 256, SMEM_REQ>>>(Bv);
    ntx_finalize<<<1, 256>>>((float*)d_out, Bv);
}